// round 1
// baseline (speedup 1.0000x reference)
#include <cuda_runtime.h>
#include <cuda_bf16.h>

// One-hot: x [8,1024] int32 -> out [8,1024,32000] fp32.
// Pure store-bandwidth problem: 1.048 GB of output per call.
// Strategy: STG.128 streaming zeros, with the single hot lane set to 1.0f.

static constexpr int NUM_CLASS = 32000;
static constexpr int NC4       = NUM_CLASS / 4;   // 8000 float4 per row
static constexpr int ROWS      = 8 * 1024;        // 8192

__global__ void __launch_bounds__(256)
onehot_kernel(const int* __restrict__ x, float4* __restrict__ out)
{
    const int row = blockIdx.y;
    const int j4  = blockIdx.x * 256 + threadIdx.x;
    if (j4 >= NC4) return;

    const int t = __ldg(x + row);       // uniform per block -> L1 broadcast

    float4 v = make_float4(0.f, 0.f, 0.f, 0.f);
    if ((t >> 2) == j4) {
        // set the one hot lane inside this 4-wide slot
        reinterpret_cast<float*>(&v)[t & 3] = 1.0f;
    }
    out[(long long)row * NC4 + j4] = v;
}

extern "C" void kernel_launch(void* const* d_in, const int* in_sizes, int n_in,
                              void* d_out, int out_size)
{
    const int* x = (const int*)d_in[0];
    float4* out  = (float4*)d_out;

    dim3 block(256);
    dim3 grid((NC4 + 255) / 256, ROWS);   // 32 x 8192 blocks
    onehot_kernel<<<grid, block>>>(x, out);
}

// round 2
// speedup vs baseline: 1.2478x; 1.2478x over previous
#include <cuda_runtime.h>
#include <cuda_bf16.h>

// One-hot: x [8,1024] int32 -> out [8,1024,32000] fp32 (1.048 GB of stores).
// Split into (a) a dependency-free streaming zero-fill and (b) a tiny scatter
// of the 8192 ones. The fill has zero loads, zero predicates, zero tail:
// 65,536,000 float4 == 8000 blocks x 256 threads x 32 stores exactly.

static constexpr int NUM_CLASS = 32000;
static constexpr long long TOTAL_F4 = 8LL * 1024 * NUM_CLASS / 4;  // 65,536,000
static constexpr int ROWS = 8 * 1024;                              // 8192

static constexpr int FILL_THREADS = 256;
static constexpr int FILL_ITERS   = 32;
static constexpr int FILL_BLOCKS  = (int)(TOTAL_F4 / (FILL_THREADS * FILL_ITERS)); // 8000

__global__ void __launch_bounds__(FILL_THREADS)
zero_fill_kernel(float4* __restrict__ out)
{
    // Contiguous 8192-float4 (128 KB) tile per block; thread strides by 256.
    float4* p = out + (long long)blockIdx.x * (FILL_THREADS * FILL_ITERS) + threadIdx.x;
    const float4 z = make_float4(0.f, 0.f, 0.f, 0.f);
#pragma unroll
    for (int i = 0; i < FILL_ITERS; ++i) {
        __stcs(p + i * FILL_THREADS, z);   // evict-first streaming store
    }
}

__global__ void __launch_bounds__(256)
scatter_ones_kernel(const int* __restrict__ x, float* __restrict__ out)
{
    const int row = blockIdx.x * 256 + threadIdx.x;
    if (row < ROWS) {
        const int t = __ldg(x + row);
        out[(long long)row * NUM_CLASS + t] = 1.0f;
    }
}

extern "C" void kernel_launch(void* const* d_in, const int* in_sizes, int n_in,
                              void* d_out, int out_size)
{
    const int* x = (const int*)d_in[0];

    zero_fill_kernel<<<FILL_BLOCKS, FILL_THREADS>>>((float4*)d_out);
    scatter_ones_kernel<<<(ROWS + 255) / 256, 256>>>(x, (float*)d_out);
}

// round 3
// speedup vs baseline: 1.2842x; 1.0292x over previous
#include <cuda_runtime.h>
#include <cuda_bf16.h>

// One-hot: x [8,1024] int32 -> out [8,1024,32000] fp32 (1.048 GB of stores).
// Fused single kernel: each block owns one row (8000 float4 = 320 thr x 25
// iters, exact). Zeros stream unconditionally (no dependence on the x load);
// the thread owning slot t>>2 then overwrites one lane with 1.0f. The zero
// and the one are same-thread same-address stores -> program-ordered, no
// fence and no second kernel needed.

static constexpr int NUM_CLASS = 32000;
static constexpr int NC4       = NUM_CLASS / 4;   // 8000
static constexpr int ROWS      = 8 * 1024;        // 8192

static constexpr int THREADS = 320;               // 8000 = 320 * 25 exactly
static constexpr int ITERS   = NC4 / THREADS;     // 25

__global__ void __launch_bounds__(THREADS)
onehot_fused_kernel(const int* __restrict__ x, float4* __restrict__ out)
{
    const int row = blockIdx.x;
    const int tid = threadIdx.x;

    const int t = __ldg(x + row);                 // issued early; stores below don't wait

    float4* p = out + (long long)row * NC4;
    const float4 z = make_float4(0.f, 0.f, 0.f, 0.f);

#pragma unroll
    for (int i = 0; i < ITERS; ++i) {
        __stcs(p + i * THREADS + tid, z);         // evict-first streaming store
    }

    const int s = t >> 2;                         // owning float4 slot
    if (s % THREADS == tid) {
        // same thread that zeroed slot s -> ordered overwrite
        reinterpret_cast<float*>(p + s)[t & 3] = 1.0f;
    }
}

extern "C" void kernel_launch(void* const* d_in, const int* in_sizes, int n_in,
                              void* d_out, int out_size)
{
    const int* x = (const int*)d_in[0];
    onehot_fused_kernel<<<ROWS, THREADS>>>(x, (float4*)d_out);
}